// round 13
// baseline (speedup 1.0000x reference)
#include <cuda_runtime.h>
#include <cstdint>

// Problem constants (fixed shapes per reference setup_inputs)
#define BV 4
#define CV 1024
#define HV 64
#define WV 64
#define SV (HV*WV)          // 4096 spatial positions
#define AHV 7
#define AWV 7
#define NBINS (AHV*AWV)     // 49
#define CGRP 64             // channels per block (one permuted pair-group)
#define NROI 2048
#define SPATIAL_SCALE 0.0625f

#define TR_BLOCKS (128 * 16 * 4)                // 8192 transpose role blocks
#define PAR_BLOCKS ((NROI * NBINS + 255) / 256) // 392 param role blocks

// Scratch 1: features as [B, H, W, C'] where C' is pair-permuted within each
// 64-channel group: scratch positions (2k, 2k+1) hold channels (k, k+32) of
// the group, i.e. the float2 at lane L holds channels {L, L+32}.
__device__ float g_feat_t[(size_t)BV * HV * WV * CV];

// Scratch 2: precomputed per-(roi,bin) params: { base_offset_bits, hr, wr, valid }
// base_offset excludes the channel-group offset (added per block).
__device__ float4 g_params[NROI * NBINS];   // 1.57 MB

// ---------------------------------------------------------------------------
// Pass 1 (fused): transpose+permute [B,C,H*W] -> [B,H*W,C_pairperm]  AND
// per-(roi,bin) param precompute, role selected by flat blockIdx.
// ---------------------------------------------------------------------------
__global__ __launch_bounds__(256)
void prep_kernel(const float* __restrict__ in, const float* __restrict__ rois) {
    const int bid = blockIdx.x;
    const int tid = threadIdx.x;

    if (bid < TR_BLOCKS) {
        // ---- transpose role: tile 64 channels x 32 spatial ----
        __shared__ float tile[CGRP][33];
        const int b   = bid >> 11;            // /2048
        const int c0g = (bid >> 7) & 15;      // /128 % 16
        const int s0  = (bid & 127) * 32;
        const int c0  = c0g * CGRP;
        const int tx  = tid & 31;
        const int ty  = tid >> 5;             // 0..7

        const float* src = in + (size_t)b * CV * SV;
        float* dst = g_feat_t + (size_t)b * SV * CV;

        #pragma unroll
        for (int cc = 0; cc < CGRP; cc += 8)
            tile[cc + ty][tx] = __ldcs(src + (size_t)(c0 + cc + ty) * SV + (s0 + tx));

        __syncthreads();

        // Lane tx emits the pair {tx, tx+32} for spatial s -> STG.64,
        // 32 lanes x 8B = 256B contiguous.
        #pragma unroll
        for (int s = ty; s < 32; s += 8) {
            float2 v;
            v.x = tile[tx     ][s];
            v.y = tile[tx + 32][s];
            *(float2*)(dst + (size_t)(s0 + s) * CV + c0 + 2 * tx) = v;
        }
    } else {
        // ---- param role ----
        const int idx = (bid - TR_BLOCKS) * 256 + tid;
        if (idx >= NROI * NBINS) return;
        const int n   = idx / NBINS;
        const int bin = idx % NBINS;

        const float* r = rois + (size_t)n * 5;
        const int   bi = (int)r[0];
        const float x1 = r[1] * SPATIAL_SCALE;
        const float y1 = r[2] * SPATIAL_SCALE;
        const float x2 = r[3] * SPATIAL_SCALE;
        const float y2 = r[4] * SPATIAL_SCALE;
        const float bin_w = fmaxf(x2 - x1, 0.0f) / (float)(AWV - 1);
        const float bin_h = fmaxf(y2 - y1, 0.0f) / (float)(AHV - 1);

        const int ph = bin / AWV;
        const int pw = bin % AWV;
        const float h  = y1 + (float)ph * bin_h;
        const float wq = x1 + (float)pw * bin_w;

        const float hstart = fminf(floorf(h),  (float)(HV - 2));
        const float wstart = fminf(floorf(wq), (float)(WV - 2));
        const float hr = h  - hstart;   // may exceed 1 near boundary (matches ref)
        const float wr = wq - wstart;

        const int hs = min(max((int)hstart, 0), HV - 2);
        const int ws = min(max((int)wstart, 0), WV - 2);
        const bool v = (h  >= 0.0f) && (h  < (float)HV) &&
                       (wq >= 0.0f) && (wq < (float)WV);

        const int base = ((bi * HV + hs) * WV + ws) * CV;
        g_params[idx] = make_float4(__int_as_float(base), hr, wr, v ? 1.0f : 0.0f);
    }
}

// ---------------------------------------------------------------------------
// Pass 2: RoIAlign gather + bilerp, distance-1 pipeline with float2 corners.
// Block = 128 threads (4 warps) over 64 channels of one roi. Warp w handles
// bins j = w, w+4, ...; lane L gathers the float2 {chan L, chan L+32} per
// corner. Small pipeline state (~13 regs) -> fits 12 blocks/SM (48 warps)
// without spills; in-flight 1KB/warp x 48 warps >> latency-hiding knee.
// Stage layout == contiguous output slab; STS bank = 17*lane (conflict-free).
// ---------------------------------------------------------------------------
__global__ __launch_bounds__(128, 12)
void roialign_kernel(float* __restrict__ out) {
    __shared__ float4 sp[NBINS];                       // packed params
    __shared__ alignas(16) float stage[CGRP * NBINS];  // 12544 B == output slab

    const int n    = blockIdx.y;
    const int c0   = blockIdx.x * CGRP;
    const int tid  = threadIdx.x;
    const int w    = tid >> 5;               // warp 0..3
    const int lane = tid & 31;

    if (tid < NBINS)
        sp[tid] = __ldg(&g_params[n * NBINS + tid]);
    __syncthreads();

    const float* __restrict__ f = g_feat_t;
    const int lc = c0 + 2 * lane;            // pair-permuted scratch offset

    // Prologue: bin j = w
    float4 p = sp[w];
    int off = __float_as_int(p.x) + lc;
    float2 ul = *(const float2*)(f + off);
    float2 ur = *(const float2*)(f + off + CV);
    float2 dl = *(const float2*)(f + off + WV * CV);
    float2 dr = *(const float2*)(f + off + WV * CV + CV);

    #pragma unroll
    for (int j = w; j < NBINS; j += 4) {
        // Prefetch bin j+4 while computing bin j.
        float2 uln, urn, dln, drn;
        float4 pn;
        const int jn = j + 4;
        if (jn < NBINS) {
            pn = sp[jn];
            const int on = __float_as_int(pn.x) + lc;
            uln = *(const float2*)(f + on);
            urn = *(const float2*)(f + on + CV);
            dln = *(const float2*)(f + on + WV * CV);
            drn = *(const float2*)(f + on + WV * CV + CV);
        }

        const float hr = p.y, wr = p.z, vv = p.w;
        float t, bo;
        t  = fmaf(wr, ur.x - ul.x, ul.x);
        bo = fmaf(wr, dr.x - dl.x, dl.x);
        stage[(lane     ) * NBINS + j] = fmaf(hr, bo - t, t) * vv;   // chan lane
        t  = fmaf(wr, ur.y - ul.y, ul.y);
        bo = fmaf(wr, dr.y - dl.y, dl.y);
        stage[(lane + 32) * NBINS + j] = fmaf(hr, bo - t, t) * vv;   // chan lane+32

        p = pn; ul = uln; ur = urn; dl = dln; dr = drn;
    }
    __syncthreads();

    // Coalesced float4 writeback, evict-first (.cs) streaming stores.
    // 64*49 floats = 784 float4; base (n*CV+c0)*49*4B is 16B-aligned (c0%64==0).
    float4* __restrict__ o4 = (float4*)(out + ((size_t)n * CV + c0) * NBINS);
    const float4* __restrict__ s4 = (const float4*)stage;
    #pragma unroll
    for (int i = tid; i < (CGRP * NBINS) / 4; i += 128)
        __stcs(o4 + i, s4[i]);
}

// ---------------------------------------------------------------------------
extern "C" void kernel_launch(void* const* d_in, const int* in_sizes, int n_in,
                              void* d_out, int out_size) {
    const float* features = (const float*)d_in[0];
    const float* rois     = (const float*)d_in[1];
    float* out            = (float*)d_out;

    prep_kernel<<<TR_BLOCKS + PAR_BLOCKS, 256>>>(features, rois);

    dim3 grid(CV / CGRP, NROI);           // (16, 2048)
    roialign_kernel<<<grid, 128>>>(out);
}